// round 9
// baseline (speedup 1.0000x reference)
#include <cuda_runtime.h>

// ---------------------------------------------------------------------------
// DILATE loss. B=128, T=256, D=64, gamma=0.01, alpha=0.5, eps=1e-8, BIG=1e10.
//
// Wavefront kernels: lane-band warp pipeline. Warp w owns rows i in
// [32w, 32w+31] and sweeps diagonals privately (287 each). Recurrence moves
// through registers + 1 shuffle per diagonal; the single cross-warp boundary
// value per diagonal goes through a 256-slot smem ring with acquire/release
// tag handshake. NO __syncthreads in the sweep. 8-deep register prefetch
// rings feed the diagonal-major D/R streams (coalesced 128B/warp/diag).
// ---------------------------------------------------------------------------

#define BATCH 128
#define TLEN  256
#define NDIAG 511            // 2*TLEN - 1
#define PAD   8              // diag padding each side (ring overshoot)
#define NDIAGT (NDIAG + 2 * PAD)
#define BIGV  1e10f
#define QNEG  -1e30f
// exp(x/gamma) = exp2(x * KE2);  KE2 = (1/gamma)*log2(e)
#define KE2   144.26950408889634f
// gamma * ln(2)
#define KL    0.006931471805599453f

__device__ float g_D[(size_t)BATCH * NDIAGT * TLEN];
__device__ float g_R[(size_t)BATCH * NDIAGT * TLEN];
__device__ float g_shape[BATCH];
__device__ float g_num[BATCH];
__device__ float g_den[BATCH];

__device__ __forceinline__ size_t DI(int b, int d, int i) {
    return ((size_t)b * NDIAGT + (d + PAD)) * TLEN + i;
}

__device__ __forceinline__ float ex2f_(float x) {
    float y; asm("ex2.approx.ftz.f32 %0, %1;" : "=f"(y) : "f"(x)); return y;
}
__device__ __forceinline__ float lg2f_(float x) {
    float y; asm("lg2.approx.ftz.f32 %0, %1;" : "=f"(y) : "f"(x)); return y;
}
__device__ __forceinline__ float softmin3(float z0, float z1, float z2) {
    float m = fminf(z0, fminf(z1, z2));
    float s = ex2f_((m - z0) * KE2) + ex2f_((m - z1) * KE2)
            + ex2f_((m - z2) * KE2);
    return m - KL * lg2f_(s);
}

__device__ __forceinline__ int ld_acq(const int* p) {
    int v;
    asm volatile("ld.acquire.cta.b32 %0, [%1];" : "=r"(v) : "l"(p) : "memory");
    return v;
}
__device__ __forceinline__ void st_rel(int* p, int v) {
    asm volatile("st.release.cta.b32 [%0], %1;" :: "l"(p), "r"(v) : "memory");
}

// ---------------------------------------------------------------------------
// Kernel 1: pairwise squared distances in diagonal layout (float4 smem).
// ---------------------------------------------------------------------------
__global__ __launch_bounds__(256) void dist_kernel(
    const float* __restrict__ preds, const float* __restrict__ targets)
{
    __shared__ float pool[2 * 64 * 68 + 128];
    float*  ps  = pool;                   // [64][68]
    float*  ts  = pool + 64 * 68;
    float*  pn  = pool + 2 * 64 * 68;     // [64]
    float*  tn  = pn + 64;
    float4* ps4 = (float4*)ps;            // pitch 17
    float4* ts4 = (float4*)ts;

    const int b  = blockIdx.z;
    const int i0 = blockIdx.y * 64;
    const int j0 = blockIdx.x * 64;
    const int tid = threadIdx.x;

    const float4* pb4 = (const float4*)(preds   + (size_t)b * TLEN * 64 + (size_t)i0 * 64);
    const float4* tb4 = (const float4*)(targets + (size_t)b * TLEN * 64 + (size_t)j0 * 64);

#pragma unroll
    for (int q = 0; q < 4; q++) {
        int idx = q * 256 + tid;          // 0..1023 float4s
        int r = idx >> 4, c4 = idx & 15;
        ps4[r * 17 + c4] = pb4[idx];
        ts4[r * 17 + c4] = tb4[idx];
    }
    __syncthreads();

    if (tid < 128) {
        const float* src = (tid < 64) ? ps : ts;
        float* dst = (tid < 64) ? pn : tn;
        int r = tid & 63;
        float s = 0.0f;
#pragma unroll
        for (int k = 0; k < 64; k++) { float v = src[r * 68 + k]; s = fmaf(v, v, s); }
        dst[r] = s;
    }
    __syncthreads();

    const int tx = tid & 15, ty = tid >> 4;
    const int ib = ty * 4, jb = tx * 4;

    float acc[4][4];
#pragma unroll
    for (int r = 0; r < 4; r++)
#pragma unroll
        for (int c = 0; c < 4; c++) acc[r][c] = 0.0f;

#pragma unroll 4
    for (int kq = 0; kq < 16; kq++) {
        float4 pv[4], tv[4];
#pragma unroll
        for (int r = 0; r < 4; r++) pv[r] = ps4[(ib + r) * 17 + kq];
#pragma unroll
        for (int c = 0; c < 4; c++) tv[c] = ts4[(jb + c) * 17 + kq];
#pragma unroll
        for (int r = 0; r < 4; r++)
#pragma unroll
            for (int c = 0; c < 4; c++) {
                acc[r][c] = fmaf(pv[r].x, tv[c].x, acc[r][c]);
                acc[r][c] = fmaf(pv[r].y, tv[c].y, acc[r][c]);
                acc[r][c] = fmaf(pv[r].z, tv[c].z, acc[r][c]);
                acc[r][c] = fmaf(pv[r].w, tv[c].w, acc[r][c]);
            }
    }

    float pnr[4], tnr[4];
#pragma unroll
    for (int r = 0; r < 4; r++) pnr[r] = pn[ib + r];
#pragma unroll
    for (int c = 0; c < 4; c++) tnr[c] = tn[jb + c];

    __syncthreads();

    // Stage tile diagonally: buf[tdd][ii], tdd = local i+j (0..126), pitch 65.
    float* buf = pool;
#pragma unroll
    for (int r = 0; r < 4; r++)
#pragma unroll
        for (int c = 0; c < 4; c++) {
            int ii = ib + r, jj = jb + c;
            float dv = pnr[r] + tnr[c] - 2.0f * acc[r][c];
            buf[(ii + jj) * 65 + ii] = fmaxf(dv, 0.0f);
        }
    __syncthreads();

    for (int base = 0; base < 128; base += 4) {
        int tdd = base + (tid >> 6);
        int ii  = tid & 63;
        if (tdd < 127) {
            int jj = tdd - ii;
            if (jj >= 0 && jj < 64)
                g_D[DI(b, i0 + j0 + tdd, i0 + ii)] = buf[tdd * 65 + ii];
        }
    }
}

// ---------------------------------------------------------------------------
// Kernel 2: soft-DTW forward, lane-band warp pipeline.
// Warp w: cells i = 32w + lane, diags d in [32w, 32w+286].
// Predecessors of (i, j=d-i): R[d-1][i-1] (nb), R[d-1][i] (Rp1), R[d-2][i-1] (n2).
// Lane 0's nb comes from warp w-1 via 256-slot tagged smem ring.
// ---------------------------------------------------------------------------
__global__ __launch_bounds__(256) void fwd_kernel()
{
    __shared__ float rgV[8][256];
    __shared__ int   rgT[8][256];

    const int b   = blockIdx.x;
    const int tid = threadIdx.x;
    const int w   = tid >> 5, l = tid & 31;
    const int i   = tid;                 // row owned by this thread
    const int dstart = w << 5;

    for (int q = tid; q < 8 * 256; q += 256) ((int*)rgT)[q] = -1;
    __syncthreads();

    const float* Dp = g_D + ((size_t)b * NDIAGT + PAD) * TLEN + i;
    float*       Rp = g_R + ((size_t)b * NDIAGT + PAD) * TLEN + i;

    float ringD[8];
#pragma unroll
    for (int k = 0; k < 8; k++) ringD[k] = Dp[(size_t)(dstart + k) * TLEN];

    float Rp1 = BIGV;   // R[d-1][i]
    float n2  = BIGV;   // R[d-2][i-1]
    float Rres = BIGV;

    auto step = [&](int d, int k) {
        float Dv = ringD[k];
        ringD[k] = Dp[(size_t)(d + 8) * TLEN];

        float nb;
        float sh = __shfl_up_sync(0xFFFFFFFFu, Rp1, 1);
        if (l == 0) {
            nb = BIGV;
            if (w > 0 && d <= dstart + 255) {
                int slot = (d - 1) & 255;
                const int* tp = &rgT[w - 1][slot];
                int tg;
                do { tg = ld_acq(tp); } while (tg != d - 1);
                nb = rgV[w - 1][slot];
            }
        } else {
            nb = sh;
        }

        float R = Dv + softmin3(n2, nb, Rp1);
        if (d == 0) R = Dv;                       // cell (0,0)
        if ((unsigned)(d - i) > 255u) R = BIGV;   // invalid cell

        Rp[(size_t)d * TLEN] = R;
        if (l == 31) {
            rgV[w][d & 255] = R;
            st_rel(&rgT[w][d & 255], d);
        }
        n2 = nb; Rp1 = R; Rres = R;
    };

    int d = dstart;
#pragma unroll 1
    for (int g = 0; g < 35; g++) {
#pragma unroll
        for (int k = 0; k < 8; k++) { step(d, k); d++; }
    }
#pragma unroll
    for (int k = 0; k < 7; k++) { step(d, k); d++; }

    if (i == 255) g_shape[b] = Rres;   // R[255,255] (warp 7 lane 31, d=510)
}

// ---------------------------------------------------------------------------
// Kernel 3: soft-DTW gradient, reverse lane-band warp pipeline.
// Warp w: cells i = 32w + lane, diags d from 32w+286 down to 32w.
// Successors of (i, j=d-i): (i+1,j)=E[d+1][i+1] (m1), (i,j+1)=E[d+1][i] (own),
// (i+1,j+1)=E[d+2][i+1] (m2).  Q = (R-D)*KE2; weight = ex2(Q_succ - R*KE2).
// Lane 31's m1 comes from warp w+1 via tagged smem ring.
// ---------------------------------------------------------------------------
__global__ __launch_bounds__(256) void bwd_kernel()
{
    __shared__ float rbE[8][256];
    __shared__ float rbQ[8][256];
    __shared__ int   rbT[8][256];
    __shared__ float red[16];

    const int b   = blockIdx.x;
    const int tid = threadIdx.x;
    const int w   = tid >> 5, l = tid & 31;
    const int i   = tid;
    const int dtop = (w << 5) + 286;

    for (int q = tid; q < 8 * 256; q += 256) ((int*)rbT)[q] = -1;
    __syncthreads();

    const float* Rp = g_R + ((size_t)b * NDIAGT + PAD) * TLEN + i;
    const float* Dp = g_D + ((size_t)b * NDIAGT + PAD) * TLEN + i;

    float ringR[8], ringD[8];
#pragma unroll
    for (int k = 0; k < 8; k++) {
        size_t off = (size_t)(dtop - k) * TLEN;
        ringR[k] = Rp[off];
        ringD[k] = Dp[off];
    }

    float Eown = 0.0f, Qown = QNEG;   // (E,Q)[d+1][i]
    float m2E  = 0.0f, m2Q  = QNEG;   // (E,Q)[d+2][i+1]
    float accS = 0.0f, accW = 0.0f;

    auto step = [&](int d, int k) {
        float R0 = ringR[k], D0 = ringD[k];
        ringR[k] = Rp[(size_t)(d - 8) * TLEN];
        ringD[k] = Dp[(size_t)(d - 8) * TLEN];

        float sE = __shfl_down_sync(0xFFFFFFFFu, Eown, 1);
        float sQ = __shfl_down_sync(0xFFFFFFFFu, Qown, 1);
        float m1E, m1Q;
        if (l == 31) {
            m1E = 0.0f; m1Q = QNEG;
            if (w < 7 && d >= i) {              // successor row i+1 exists & valid j
                int slot = (d + 1) & 255;
                const int* tp = &rbT[w + 1][slot];
                int tg;
                do { tg = ld_acq(tp); } while (tg != d + 1);
                m1E = rbE[w + 1][slot];
                m1Q = rbQ[w + 1][slot];
            }
        } else {
            m1E = sE; m1Q = sQ;
        }

        float E, Q;
        if ((unsigned)(d - i) <= 255u) {
            float t = R0 * KE2;
            Q = (R0 - D0) * KE2;
            E =            m1E  * ex2f_(m1Q  - t);
            E = fmaf(Eown, ex2f_(Qown - t), E);
            E = fmaf(m2E,  ex2f_(m2Q  - t), E);
            if (d == 510 && l == 31) E = 1.0f;   // seed (255,255), warp 7 only
            accS += E;
            float dw = (float)(2 * i - d);        // i - j
            accW = fmaf(E, dw * dw, accW);
        } else {
            E = 0.0f; Q = QNEG;
        }

        if (l == 0) {
            rbE[w][d & 255] = E;
            rbQ[w][d & 255] = Q;
            st_rel(&rbT[w][d & 255], d);
        }
        m2E = m1E; m2Q = m1Q; Eown = E; Qown = Q;
    };

    int d = dtop;
#pragma unroll 1
    for (int g = 0; g < 35; g++) {
#pragma unroll
        for (int k = 0; k < 8; k++) { step(d, k); d--; }
    }
#pragma unroll
    for (int k = 0; k < 7; k++) { step(d, k); d--; }

    accW *= (1.0f / (255.0f * 255.0f));   // omega /(T-1)^2

#pragma unroll
    for (int off = 16; off; off >>= 1) {
        accS += __shfl_down_sync(0xFFFFFFFFu, accS, off);
        accW += __shfl_down_sync(0xFFFFFFFFu, accW, off);
    }
    if (l == 0) { red[w] = accS; red[w + 8] = accW; }
    __syncthreads();
    if (tid == 0) {
        float s = 0.0f, wv = 0.0f;
#pragma unroll
        for (int q = 0; q < 8; q++) { s += red[q]; wv += red[q + 8]; }
        g_den[b] = s;
        g_num[b] = wv;
    }
}

// ---------------------------------------------------------------------------
// Kernel 4: final scalar.
// ---------------------------------------------------------------------------
__global__ void final_kernel(float* __restrict__ out)
{
    __shared__ float red[4];
    const int t = threadIdx.x;   // 128 threads, one per batch

    float shape = g_shape[t] * (1.0f / 256.0f);
    float den   = g_den[t]   * (1.0f / 256.0f);
    float num   = g_num[t]   * (1.0f / 256.0f);
    float temporal = num / fmaxf(den, 1e-8f);
    float val = 0.5f * shape + 0.5f * temporal;

#pragma unroll
    for (int off = 16; off; off >>= 1)
        val += __shfl_down_sync(0xFFFFFFFFu, val, off);
    if ((t & 31) == 0) red[t >> 5] = val;
    __syncthreads();
    if (t == 0)
        out[0] = (red[0] + red[1] + red[2] + red[3]) * (1.0f / 128.0f);
}

// ---------------------------------------------------------------------------
extern "C" void kernel_launch(void* const* d_in, const int* in_sizes, int n_in,
                              void* d_out, int out_size)
{
    const float* preds   = (const float*)d_in[0];
    const float* targets = (const float*)d_in[1];

    dist_kernel<<<dim3(4, 4, BATCH), 256>>>(preds, targets);
    fwd_kernel<<<BATCH, 256>>>();
    bwd_kernel<<<BATCH, 256>>>();
    final_kernel<<<1, 128>>>((float*)d_out);
}

// round 10
// speedup vs baseline: 3.0204x; 3.0204x over previous
#include <cuda_runtime.h>

// ---------------------------------------------------------------------------
// DILATE loss. B=128, T=256, D=64, gamma=0.01, alpha=0.5, eps=1e-8, BIG=1e10.
// Wavefront kernels: 2 diagonals per barrier, 4-phase register prefetch rings
// for all global streams (no dependent loads), PLUS warp-uniform band skip:
// a warp whose 32 rows have no valid cells on this phase's diagonals skips all
// compute/MUFU/stores and only writes boundary padding to smem.
// ---------------------------------------------------------------------------

#define BATCH 128
#define TLEN  256
#define NDIAG 511            // 2*TLEN - 1
#define PAD   8              // diag padding each side (ring overshoot)
#define NDIAGT (NDIAG + 2 * PAD)
#define BIGV  1e10f
// exp(x/gamma) = exp2(x * KE2);  KE2 = (1/gamma)*log2(e)
#define KE2   144.26950408889634f
// gamma * ln(2)
#define KL    0.006931471805599453f

__device__ float g_D[(size_t)BATCH * NDIAGT * TLEN];
__device__ float g_R[(size_t)BATCH * NDIAGT * TLEN];
__device__ float g_shape[BATCH];
__device__ float g_num[BATCH];
__device__ float g_den[BATCH];

__device__ __forceinline__ size_t DI(int b, int d, int i) {
    return ((size_t)b * NDIAGT + (d + PAD)) * TLEN + i;
}

__device__ __forceinline__ float ex2f_(float x) {
    float y; asm("ex2.approx.ftz.f32 %0, %1;" : "=f"(y) : "f"(x)); return y;
}
__device__ __forceinline__ float lg2f_(float x) {
    float y; asm("lg2.approx.ftz.f32 %0, %1;" : "=f"(y) : "f"(x)); return y;
}
__device__ __forceinline__ float softmin3(float z0, float z1, float z2) {
    float m = fminf(z0, fminf(z1, z2));
    float s = ex2f_((m - z0) * KE2) + ex2f_((m - z1) * KE2)
            + ex2f_((m - z2) * KE2);
    return m - KL * lg2f_(s);
}

// ---------------------------------------------------------------------------
// Kernel 1: pairwise squared distances in diagonal layout (float4 smem).
// ---------------------------------------------------------------------------
__global__ __launch_bounds__(256) void dist_kernel(
    const float* __restrict__ preds, const float* __restrict__ targets)
{
    __shared__ float pool[2 * 64 * 68 + 128];
    float*  ps  = pool;                   // [64][68]
    float*  ts  = pool + 64 * 68;
    float*  pn  = pool + 2 * 64 * 68;     // [64]
    float*  tn  = pn + 64;
    float4* ps4 = (float4*)ps;            // pitch 17
    float4* ts4 = (float4*)ts;

    const int b  = blockIdx.z;
    const int i0 = blockIdx.y * 64;
    const int j0 = blockIdx.x * 64;
    const int tid = threadIdx.x;

    const float4* pb4 = (const float4*)(preds   + (size_t)b * TLEN * 64 + (size_t)i0 * 64);
    const float4* tb4 = (const float4*)(targets + (size_t)b * TLEN * 64 + (size_t)j0 * 64);

#pragma unroll
    for (int q = 0; q < 4; q++) {
        int idx = q * 256 + tid;          // 0..1023 float4s
        int r = idx >> 4, c4 = idx & 15;
        ps4[r * 17 + c4] = pb4[idx];
        ts4[r * 17 + c4] = tb4[idx];
    }
    __syncthreads();

    if (tid < 128) {
        const float* src = (tid < 64) ? ps : ts;
        float* dst = (tid < 64) ? pn : tn;
        int r = tid & 63;
        float s = 0.0f;
#pragma unroll
        for (int k = 0; k < 64; k++) { float v = src[r * 68 + k]; s = fmaf(v, v, s); }
        dst[r] = s;
    }
    __syncthreads();

    const int tx = tid & 15, ty = tid >> 4;
    const int ib = ty * 4, jb = tx * 4;

    float acc[4][4];
#pragma unroll
    for (int r = 0; r < 4; r++)
#pragma unroll
        for (int c = 0; c < 4; c++) acc[r][c] = 0.0f;

#pragma unroll 4
    for (int kq = 0; kq < 16; kq++) {
        float4 pv[4], tv[4];
#pragma unroll
        for (int r = 0; r < 4; r++) pv[r] = ps4[(ib + r) * 17 + kq];
#pragma unroll
        for (int c = 0; c < 4; c++) tv[c] = ts4[(jb + c) * 17 + kq];
#pragma unroll
        for (int r = 0; r < 4; r++)
#pragma unroll
            for (int c = 0; c < 4; c++) {
                acc[r][c] = fmaf(pv[r].x, tv[c].x, acc[r][c]);
                acc[r][c] = fmaf(pv[r].y, tv[c].y, acc[r][c]);
                acc[r][c] = fmaf(pv[r].z, tv[c].z, acc[r][c]);
                acc[r][c] = fmaf(pv[r].w, tv[c].w, acc[r][c]);
            }
    }

    float pnr[4], tnr[4];
#pragma unroll
    for (int r = 0; r < 4; r++) pnr[r] = pn[ib + r];
#pragma unroll
    for (int c = 0; c < 4; c++) tnr[c] = tn[jb + c];

    __syncthreads();

    // Stage tile diagonally: buf[tdd][ii], tdd = local i+j (0..126), pitch 65.
    float* buf = pool;
#pragma unroll
    for (int r = 0; r < 4; r++)
#pragma unroll
        for (int c = 0; c < 4; c++) {
            int ii = ib + r, jj = jb + c;
            float dv = pnr[r] + tnr[c] - 2.0f * acc[r][c];
            buf[(ii + jj) * 65 + ii] = fmaxf(dv, 0.0f);
        }
    __syncthreads();

    for (int base = 0; base < 128; base += 4) {
        int tdd = base + (tid >> 6);
        int ii  = tid & 63;
        if (tdd < 127) {
            int jj = tdd - ii;
            if (jj >= 0 && jj < 64)
                g_D[DI(b, i0 + j0 + tdd, i0 + ii)] = buf[tdd * 65 + ii];
        }
    }
}

// ---------------------------------------------------------------------------
// Kernel 2: soft-DTW forward. 2 diagonals per barrier (halo X = R[d][i-1]),
// warp-uniform band skip: warp w active only for d in [32w-1, 32w+286].
// ---------------------------------------------------------------------------
__global__ __launch_bounds__(256) void fwd_kernel()
{
    __shared__ float sR[4][260];   // R[dd][k] at sR[dd&3][k+2]; [0..1] = BIG pad
    const int b = blockIdx.x;
    const int i = threadIdx.x;
    const int w = i >> 5;
    const int blo = (w << 5) - 1;        // active band of this warp
    const int bhi = (w << 5) + 286;

    for (int q = i; q < 4 * 260; q += 256) ((float*)sR)[q] = BIGV;
    __syncthreads();

    const float* Dbase  = g_D + ((size_t)b * NDIAGT + PAD) * TLEN;
    const float* Dp     = Dbase + i;
    const float* DpH    = Dbase + i - 1;   // halo column (pad rows keep i=0 safe)
    float*       Rp     = g_R + ((size_t)b * NDIAGT + PAD) * TLEN + i;

    float rA[4], rB[4], rH[4];
#pragma unroll
    for (int k = 0; k < 4; k++) {
        rA[k] = Dp[(2 * k) * TLEN];
        rB[k] = Dp[(2 * k + 1) * TLEN];
        rH[k] = DpH[(2 * k) * TLEN];
    }

    auto fstep = [&](int p, int k) {
        const int d = 2 * p;
        float DY = rA[k], DZ = rB[k], DXv = rH[k];
        rA[k] = Dp[(d + 8) * TLEN];
        rB[k] = Dp[(d + 9) * TLEN];
        rH[k] = DpH[(d + 8) * TLEN];

        if (d >= blo && d <= bhi) {        // warp-uniform: any valid work?
            const float* rm1 = sR[(d + 3) & 3];  // diag d-1
            const float* rm2 = sR[(d + 2) & 3];  // diag d-2

            // X = R[d][i-1] (halo)
            bool vX = (i >= 1) && (i <= d + 1) && (d - i < 255);
            float x = softmin3(rm2[i], rm1[i], rm1[i + 1]) + DXv;
            if (d == 0) x = DXv;          // cell (0,0) when vX (i==1)
            if (!vX) x = BIGV;

            // Y = R[d][i]
            bool vY = (i <= d) && (d - i < 256);
            float z1y = rm1[i + 1];
            float y = softmin3(rm2[i + 1], z1y, rm1[i + 2]) + DY;
            if (d == 0 && i == 0) y = DY;
            if (!vY) y = BIGV;

            // Z = R[d+1][i]  (needs R[d-1][i-1]=z1y, X, Y)
            bool vZ = (i <= d + 1) && (d - i < 255);
            float z = softmin3(z1y, x, y) + DZ;
            if (!vZ) z = BIGV;

            Rp[(size_t)d * TLEN]       = y;
            Rp[(size_t)(d + 1) * TLEN] = z;
            sR[d & 3][i + 2]       = y;
            sR[(d + 1) & 3][i + 2] = z;
        } else {
            // out-of-band: keep boundary padding correct for neighbor warps
            sR[d & 3][i + 2]       = BIGV;
            sR[(d + 1) & 3][i + 2] = BIGV;
        }
        __syncthreads();
    };

#pragma unroll 1
    for (int g = 0; g < 63; g++) {
#pragma unroll
        for (int k = 0; k < 4; k++) fstep(g * 4 + k, k);
    }
    fstep(252, 0); fstep(253, 1); fstep(254, 2);

    // Epilogue: diag 510.
    {
        const int d = 510;
        float DY = rA[3];
        const float* rm1 = sR[(d + 3) & 3];
        const float* rm2 = sR[(d + 2) & 3];
        float y = softmin3(rm2[i + 1], rm1[i + 1], rm1[i + 2]) + DY;
        if (i < 255) y = BIGV;
        Rp[(size_t)d * TLEN] = y;
        if (i == 255) g_shape[b] = y;   // R[255,255]
    }
}

// ---------------------------------------------------------------------------
// Kernel 3: soft-DTW gradient, reverse. 2 diagonals per barrier
// (halo X = E[d][i+1]), warp-uniform band skip (d in [32w, 32w+287]).
// Q = (R - D) * KE2.
// ---------------------------------------------------------------------------
__global__ __launch_bounds__(256) void bwd_kernel()
{
    __shared__ float sE[4][260];   // position k at [k]; [256..259] = 0 pad
    __shared__ float sQ[4][260];
    __shared__ float red[16];

    const int b = blockIdx.x;
    const int i = threadIdx.x;
    const int w = i >> 5;
    const int blo = (w << 5);            // active band of this warp
    const int bhi = (w << 5) + 287;

    for (int q = i; q < 4 * 260; q += 256) {
        ((float*)sE)[q] = 0.0f;
        ((float*)sQ)[q] = 0.0f;
    }
    __syncthreads();

    const float* Rbase = g_R + ((size_t)b * NDIAGT + PAD) * TLEN;
    const float* Dbase = g_D + ((size_t)b * NDIAGT + PAD) * TLEN;
    const float* Rp  = Rbase + i;
    const float* Dp  = Dbase + i;
    const float* RpX = Rbase + i + 1;   // halo column (pad rows keep i=255 safe)
    const float* DpX = Dbase + i + 1;

    float rR0[4], rD0[4], rR1[4], rD1[4], rRx[4], rDx[4];
#pragma unroll
    for (int k = 0; k < 4; k++) {
        rR0[k] = Rp[(size_t)(510 - 2 * k) * TLEN];
        rD0[k] = Dp[(size_t)(510 - 2 * k) * TLEN];
        rR1[k] = Rp[(size_t)(509 - 2 * k) * TLEN];
        rD1[k] = Dp[(size_t)(509 - 2 * k) * TLEN];
        rRx[k] = RpX[(size_t)(510 - 2 * k) * TLEN];
        rDx[k] = DpX[(size_t)(510 - 2 * k) * TLEN];
    }

    float accS = 0.0f, accW = 0.0f;

    auto bstep = [&](int p, int k) {
        const int d = 510 - 2 * p;
        float R0 = rR0[k], D0 = rD0[k], R1 = rR1[k], D1 = rD1[k];
        float Rx = rRx[k], Dx = rDx[k];
        rR0[k] = Rp[(size_t)(d - 8) * TLEN];
        rD0[k] = Dp[(size_t)(d - 8) * TLEN];
        rR1[k] = Rp[(size_t)(d - 9) * TLEN];
        rD1[k] = Dp[(size_t)(d - 9) * TLEN];
        rRx[k] = RpX[(size_t)(d - 8) * TLEN];
        rDx[k] = DpX[(size_t)(d - 8) * TLEN];

        if (d >= blo && d <= bhi) {        // warp-uniform: any valid work?
            const int j = d - i;
            const float* eN1 = sE[(d + 1) & 3]; const float* qN1 = sQ[(d + 1) & 3];
            const float* eN2 = sE[(d + 2) & 3]; const float* qN2 = sQ[(d + 2) & 3];

            // Y = E[d][i]
            bool vY = (i <= d) && (j < 256);
            float Y = 0.0f;
            if (vY) {
                float tY = R0 * KE2;
                float e = 0.0f;
                if (i < 255) e = fmaf(eN1[i + 1], ex2f_(qN1[i + 1] - tY), e);
                if (j < 255) e = fmaf(eN1[i],     ex2f_(qN1[i]     - tY), e);
                if (i < 255 && j < 255)
                             e = fmaf(eN2[i + 1], ex2f_(qN2[i + 1] - tY), e);
                Y = e;
            }
            if (d == 510) Y = (i == 255) ? 1.0f : 0.0f;

            // X = E[d][i+1] (halo)
            bool vX = (i < 255) && (i + 1 <= d) && (d - i - 1 < 256);
            float X = 0.0f;
            if (vX) {
                float tX = Rx * KE2;
                float e = 0.0f;
                if (i + 1 < 255) e = fmaf(eN1[i + 2], ex2f_(qN1[i + 2] - tX), e);
                if (j - 1 < 255) e = fmaf(eN1[i + 1], ex2f_(qN1[i + 1] - tX), e);
                if (i + 1 < 255 && j - 1 < 255)
                                 e = fmaf(eN2[i + 2], ex2f_(qN2[i + 2] - tX), e);
                X = e;
            }
            if (d == 510) X = (i + 1 == 255) ? 1.0f : 0.0f;

            // Z = E[d-1][i]
            float QY = (R0 - D0) * KE2;
            float QX = (Rx - Dx) * KE2;
            bool vZ = (i <= d - 1) && (d - 1 - i < 256);
            float Z = 0.0f;
            if (vZ) {
                float tZ = R1 * KE2;
                float e = 0.0f;
                if (i < 255)         e = fmaf(X, ex2f_(QX - tZ), e);
                if (d - 1 - i < 255) e = fmaf(Y, ex2f_(QY - tZ), e);
                if (i < 255 && d - 1 - i < 255)
                                     e = fmaf(eN1[i + 1], ex2f_(qN1[i + 1] - tZ), e);
                Z = e;
            }

            if (vY) { accS += Y; float dw = (float)(i - j);       accW = fmaf(Y, dw * dw, accW); }
            if (vZ) { accS += Z; float dw = (float)(i - (j - 1)); accW = fmaf(Z, dw * dw, accW); }

            sE[d & 3][i] = Y;       sQ[d & 3][i] = QY;
            sE[(d - 1) & 3][i] = Z; sQ[(d - 1) & 3][i] = (R1 - D1) * KE2;
        } else {
            // out-of-band: keep zero padding correct for neighbor warps
            sE[d & 3][i] = 0.0f;       sQ[d & 3][i] = 0.0f;
            sE[(d - 1) & 3][i] = 0.0f; sQ[(d - 1) & 3][i] = 0.0f;
        }
        __syncthreads();
    };

#pragma unroll 1
    for (int g = 0; g < 63; g++) {
#pragma unroll
        for (int k = 0; k < 4; k++) bstep(g * 4 + k, k);
    }
    bstep(252, 0); bstep(253, 1); bstep(254, 2);

    // Epilogue: diag 0 (cell (0,0); omega weight = 0).
    if (i == 0) {
        float tY = rR0[3] * KE2;
        float e = 0.0f;
        e = fmaf(sE[1][1], ex2f_(sQ[1][1] - tY), e);
        e = fmaf(sE[1][0], ex2f_(sQ[1][0] - tY), e);
        e = fmaf(sE[2][1], ex2f_(sQ[2][1] - tY), e);
        accS += e;
    }

    accW *= (1.0f / (255.0f * 255.0f));

#pragma unroll
    for (int off = 16; off; off >>= 1) {
        accS += __shfl_down_sync(0xFFFFFFFFu, accS, off);
        accW += __shfl_down_sync(0xFFFFFFFFu, accW, off);
    }
    const int l = i & 31;
    if (l == 0) { red[w] = accS; red[w + 8] = accW; }
    __syncthreads();
    if (i == 0) {
        float s = 0.0f, wv = 0.0f;
#pragma unroll
        for (int q = 0; q < 8; q++) { s += red[q]; wv += red[q + 8]; }
        g_den[b] = s;
        g_num[b] = wv;
    }
}

// ---------------------------------------------------------------------------
// Kernel 4: final scalar.
// ---------------------------------------------------------------------------
__global__ void final_kernel(float* __restrict__ out)
{
    __shared__ float red[4];
    const int t = threadIdx.x;   // 128 threads, one per batch

    float shape = g_shape[t] * (1.0f / 256.0f);
    float den   = g_den[t]   * (1.0f / 256.0f);
    float num   = g_num[t]   * (1.0f / 256.0f);
    float temporal = num / fmaxf(den, 1e-8f);
    float val = 0.5f * shape + 0.5f * temporal;

#pragma unroll
    for (int off = 16; off; off >>= 1)
        val += __shfl_down_sync(0xFFFFFFFFu, val, off);
    if ((t & 31) == 0) red[t >> 5] = val;
    __syncthreads();
    if (t == 0)
        out[0] = (red[0] + red[1] + red[2] + red[3]) * (1.0f / 128.0f);
}

// ---------------------------------------------------------------------------
extern "C" void kernel_launch(void* const* d_in, const int* in_sizes, int n_in,
                              void* d_out, int out_size)
{
    const float* preds   = (const float*)d_in[0];
    const float* targets = (const float*)d_in[1];

    dist_kernel<<<dim3(4, 4, BATCH), 256>>>(preds, targets);
    fwd_kernel<<<BATCH, 256>>>();
    bwd_kernel<<<BATCH, 256>>>();
    final_kernel<<<1, 128>>>((float*)d_out);
}

// round 11
// speedup vs baseline: 3.2372x; 1.0718x over previous
#include <cuda_runtime.h>

// ---------------------------------------------------------------------------
// DILATE loss. B=128, T=256, D=64, gamma=0.01, alpha=0.5, eps=1e-8, BIG=1e10.
// Wavefront kernels: 2 diagonals per barrier, 4-phase register prefetch rings
// (no dependent loads), DEFERRED global stores (issued just after a barrier,
// retire during the next phase), and vector-packed ping-pong smem state
// (float2 in fwd, float4 in bwd) to minimize STS drain cost at barriers.
// ---------------------------------------------------------------------------

#define BATCH 128
#define TLEN  256
#define NDIAG 511            // 2*TLEN - 1
#define PAD   8              // diag padding each side (ring overshoot)
#define NDIAGT (NDIAG + 2 * PAD)
#define BIGV  1e10f
// exp(x/gamma) = exp2(x * KE2);  KE2 = (1/gamma)*log2(e)
#define KE2   144.26950408889634f
// gamma * ln(2)
#define KL    0.006931471805599453f

__device__ float g_D[(size_t)BATCH * NDIAGT * TLEN];
__device__ float g_R[(size_t)BATCH * NDIAGT * TLEN];
__device__ float g_shape[BATCH];
__device__ float g_num[BATCH];
__device__ float g_den[BATCH];

__device__ __forceinline__ size_t DI(int b, int d, int i) {
    return ((size_t)b * NDIAGT + (d + PAD)) * TLEN + i;
}

__device__ __forceinline__ float ex2f_(float x) {
    float y; asm("ex2.approx.ftz.f32 %0, %1;" : "=f"(y) : "f"(x)); return y;
}
__device__ __forceinline__ float lg2f_(float x) {
    float y; asm("lg2.approx.ftz.f32 %0, %1;" : "=f"(y) : "f"(x)); return y;
}
__device__ __forceinline__ float softmin3(float z0, float z1, float z2) {
    float m = fminf(z0, fminf(z1, z2));
    float s = ex2f_((m - z0) * KE2) + ex2f_((m - z1) * KE2)
            + ex2f_((m - z2) * KE2);
    return m - KL * lg2f_(s);
}

// ---------------------------------------------------------------------------
// Kernel 1: pairwise squared distances in diagonal layout (float4 smem).
// ---------------------------------------------------------------------------
__global__ __launch_bounds__(256) void dist_kernel(
    const float* __restrict__ preds, const float* __restrict__ targets)
{
    __shared__ float pool[2 * 64 * 68 + 128];
    float*  ps  = pool;                   // [64][68]
    float*  ts  = pool + 64 * 68;
    float*  pn  = pool + 2 * 64 * 68;     // [64]
    float*  tn  = pn + 64;
    float4* ps4 = (float4*)ps;            // pitch 17
    float4* ts4 = (float4*)ts;

    const int b  = blockIdx.z;
    const int i0 = blockIdx.y * 64;
    const int j0 = blockIdx.x * 64;
    const int tid = threadIdx.x;

    const float4* pb4 = (const float4*)(preds   + (size_t)b * TLEN * 64 + (size_t)i0 * 64);
    const float4* tb4 = (const float4*)(targets + (size_t)b * TLEN * 64 + (size_t)j0 * 64);

#pragma unroll
    for (int q = 0; q < 4; q++) {
        int idx = q * 256 + tid;          // 0..1023 float4s
        int r = idx >> 4, c4 = idx & 15;
        ps4[r * 17 + c4] = pb4[idx];
        ts4[r * 17 + c4] = tb4[idx];
    }
    __syncthreads();

    if (tid < 128) {
        const float* src = (tid < 64) ? ps : ts;
        float* dst = (tid < 64) ? pn : tn;
        int r = tid & 63;
        float s = 0.0f;
#pragma unroll
        for (int k = 0; k < 64; k++) { float v = src[r * 68 + k]; s = fmaf(v, v, s); }
        dst[r] = s;
    }
    __syncthreads();

    const int tx = tid & 15, ty = tid >> 4;
    const int ib = ty * 4, jb = tx * 4;

    float acc[4][4];
#pragma unroll
    for (int r = 0; r < 4; r++)
#pragma unroll
        for (int c = 0; c < 4; c++) acc[r][c] = 0.0f;

#pragma unroll 4
    for (int kq = 0; kq < 16; kq++) {
        float4 pv[4], tv[4];
#pragma unroll
        for (int r = 0; r < 4; r++) pv[r] = ps4[(ib + r) * 17 + kq];
#pragma unroll
        for (int c = 0; c < 4; c++) tv[c] = ts4[(jb + c) * 17 + kq];
#pragma unroll
        for (int r = 0; r < 4; r++)
#pragma unroll
            for (int c = 0; c < 4; c++) {
                acc[r][c] = fmaf(pv[r].x, tv[c].x, acc[r][c]);
                acc[r][c] = fmaf(pv[r].y, tv[c].y, acc[r][c]);
                acc[r][c] = fmaf(pv[r].z, tv[c].z, acc[r][c]);
                acc[r][c] = fmaf(pv[r].w, tv[c].w, acc[r][c]);
            }
    }

    float pnr[4], tnr[4];
#pragma unroll
    for (int r = 0; r < 4; r++) pnr[r] = pn[ib + r];
#pragma unroll
    for (int c = 0; c < 4; c++) tnr[c] = tn[jb + c];

    __syncthreads();

    // Stage tile diagonally: buf[tdd][ii], tdd = local i+j (0..126), pitch 65.
    float* buf = pool;
#pragma unroll
    for (int r = 0; r < 4; r++)
#pragma unroll
        for (int c = 0; c < 4; c++) {
            int ii = ib + r, jj = jb + c;
            float dv = pnr[r] + tnr[c] - 2.0f * acc[r][c];
            buf[(ii + jj) * 65 + ii] = fmaxf(dv, 0.0f);
        }
    __syncthreads();

    for (int base = 0; base < 128; base += 4) {
        int tdd = base + (tid >> 6);
        int ii  = tid & 63;
        if (tdd < 127) {
            int jj = tdd - ii;
            if (jj >= 0 && jj < 64)
                g_D[DI(b, i0 + j0 + tdd, i0 + ii)] = buf[tdd * 65 + ii];
        }
    }
}

// ---------------------------------------------------------------------------
// Kernel 2: soft-DTW forward. Phase p computes diags d=2p (Y), d+1 (Z) with
// halo X = R[d][i-1]. Ping-pong float2 smem: sP[p&1][i+2] = (R[d][i], R[d+1][i]).
// Global stores of phase p-1 issued at top of phase p (post-barrier).
// ---------------------------------------------------------------------------
__global__ __launch_bounds__(256) void fwd_kernel()
{
    __shared__ float2 sP[2][260];   // [0..1] = BIG pad (never overwritten)
    const int b = blockIdx.x;
    const int i = threadIdx.x;

    for (int q = i; q < 2 * 260 * 2; q += 256) ((float*)sP)[q] = BIGV;
    __syncthreads();

    const float* Dbase  = g_D + ((size_t)b * NDIAGT + PAD) * TLEN;
    const float* Dp     = Dbase + i;
    const float* DpH    = Dbase + i - 1;   // halo column (pad rows keep i=0 safe)
    float*       Rp     = g_R + ((size_t)b * NDIAGT + PAD) * TLEN + i;

    float rA[4], rB[4], rH[4];
#pragma unroll
    for (int k = 0; k < 4; k++) {
        rA[k] = Dp[(2 * k) * TLEN];
        rB[k] = Dp[(2 * k + 1) * TLEN];
        rH[k] = DpH[(2 * k) * TLEN];
    }

    float qy = 0.0f, qz = 0.0f;   // deferred store queue (phase p-1's y,z)

    auto fstep = [&](int p, int k) {
        const int d = 2 * p;
        // Deferred global stores of previous phase (issued just after barrier,
        // retire during this phase's compute — off the barrier-drain path).
        if (p >= 1) {
            Rp[(size_t)(d - 2) * TLEN] = qy;
            Rp[(size_t)(d - 1) * TLEN] = qz;
        }

        float DY = rA[k], DZ = rB[k], DXv = rH[k];
        rA[k] = Dp[(d + 8) * TLEN];
        rB[k] = Dp[(d + 9) * TLEN];
        rH[k] = DpH[(d + 8) * TLEN];

        const float2* sPp = sP[(p + 1) & 1];
        float2 P0 = sPp[i];       // (R[d-2][i-2], R[d-1][i-2])
        float2 P1 = sPp[i + 1];   // (R[d-2][i-1], R[d-1][i-1])
        float2 P2 = sPp[i + 2];   // (R[d-2][i],   R[d-1][i])

        // X = R[d][i-1] (halo)
        bool vX = (i >= 1) && (i <= d + 1) && (d - i < 255);
        float x = softmin3(P0.x, P0.y, P1.y) + DXv;
        if (d == 0) x = DXv;          // cell (0,0) when vX (i==1)
        if (!vX) x = BIGV;

        // Y = R[d][i]
        bool vY = (i <= d) && (d - i < 256);
        float y = softmin3(P1.x, P1.y, P2.y) + DY;
        if (d == 0 && i == 0) y = DY;
        if (!vY) y = BIGV;

        // Z = R[d+1][i]  (preds: R[d-1][i-1]=P1.y, X, Y)
        bool vZ = (i <= d + 1) && (d - i < 255);
        float z = softmin3(P1.y, x, y) + DZ;
        if (!vZ) z = BIGV;

        sP[p & 1][i + 2] = make_float2(y, z);
        qy = y; qz = z;
        __syncthreads();
    };

#pragma unroll 1
    for (int g = 0; g < 63; g++) {
#pragma unroll
        for (int k = 0; k < 4; k++) fstep(g * 4 + k, k);
    }
    fstep(252, 0); fstep(253, 1); fstep(254, 2);

    // Flush phase 254's deferred stores.
    Rp[(size_t)508 * TLEN] = qy;
    Rp[(size_t)509 * TLEN] = qz;

    // Epilogue: diag 510 (reads phase 254's buffer = sP[0]).
    {
        const float2* sPp = sP[0];
        float y = softmin3(sPp[i + 1].x, sPp[i + 1].y, sPp[i + 2].y) + rA[3];
        if (i < 255) y = BIGV;
        Rp[(size_t)510 * TLEN] = y;
        if (i == 255) g_shape[b] = y;   // R[255,255]
    }
}

// ---------------------------------------------------------------------------
// Kernel 3: soft-DTW gradient, reverse. Phase p computes diags d=510-2p (Y)
// and d-1 (Z) with halo X = E[d][i+1]. Ping-pong float4 smem:
// sP4[p&1][i] = (E_d[i], Q_d[i], E_{d-1}[i], Q_{d-1}[i]),  Q = (R-D)*KE2.
// ---------------------------------------------------------------------------
__global__ __launch_bounds__(256) void bwd_kernel()
{
    __shared__ float4 sP4[2][258];   // [256..257] = zero pad (never overwritten)
    __shared__ float red[16];

    const int b = blockIdx.x;
    const int i = threadIdx.x;

    for (int q = i; q < 2 * 258 * 4; q += 256) ((float*)sP4)[q] = 0.0f;
    __syncthreads();

    const float* Rbase = g_R + ((size_t)b * NDIAGT + PAD) * TLEN;
    const float* Dbase = g_D + ((size_t)b * NDIAGT + PAD) * TLEN;
    const float* Rp  = Rbase + i;
    const float* Dp  = Dbase + i;
    const float* RpX = Rbase + i + 1;   // halo column (pad rows keep i=255 safe)
    const float* DpX = Dbase + i + 1;

    float rR0[4], rD0[4], rR1[4], rD1[4], rRx[4], rDx[4];
#pragma unroll
    for (int k = 0; k < 4; k++) {
        rR0[k] = Rp[(size_t)(510 - 2 * k) * TLEN];
        rD0[k] = Dp[(size_t)(510 - 2 * k) * TLEN];
        rR1[k] = Rp[(size_t)(509 - 2 * k) * TLEN];
        rD1[k] = Dp[(size_t)(509 - 2 * k) * TLEN];
        rRx[k] = RpX[(size_t)(510 - 2 * k) * TLEN];
        rDx[k] = DpX[(size_t)(510 - 2 * k) * TLEN];
    }

    float accS = 0.0f, accW = 0.0f;

    auto bstep = [&](int p, int k) {
        const int d = 510 - 2 * p;
        float R0 = rR0[k], D0 = rD0[k], R1 = rR1[k], D1 = rD1[k];
        float Rx = rRx[k], Dx = rDx[k];
        rR0[k] = Rp[(size_t)(d - 8) * TLEN];
        rD0[k] = Dp[(size_t)(d - 8) * TLEN];
        rR1[k] = Rp[(size_t)(d - 9) * TLEN];
        rD1[k] = Dp[(size_t)(d - 9) * TLEN];
        rRx[k] = RpX[(size_t)(d - 8) * TLEN];
        rDx[k] = DpX[(size_t)(d - 8) * TLEN];

        const int j = d - i;
        const float4* sPp = sP4[(p + 1) & 1];
        float4 A0 = sPp[i];       // (E[d+2][i],   Q[d+2][i],   E[d+1][i],   Q[d+1][i])
        float4 A1 = sPp[i + 1];
        float4 A2 = sPp[i + 2];

        // Y = E[d][i]
        bool vY = (i <= d) && (j < 256);
        float Y = 0.0f;
        if (vY) {
            float tY = R0 * KE2;
            float e = 0.0f;
            if (i < 255) e = fmaf(A1.z, ex2f_(A1.w - tY), e);   // (i+1, j)
            if (j < 255) e = fmaf(A0.z, ex2f_(A0.w - tY), e);   // (i, j+1)
            if (i < 255 && j < 255)
                         e = fmaf(A1.x, ex2f_(A1.y - tY), e);   // (i+1, j+1)
            Y = e;
        }
        if (d == 510) Y = (i == 255) ? 1.0f : 0.0f;

        // X = E[d][i+1] (halo)
        bool vX = (i < 255) && (i + 1 <= d) && (d - i - 1 < 256);
        float X = 0.0f;
        if (vX) {
            float tX = Rx * KE2;
            float e = 0.0f;
            if (i + 1 < 255) e = fmaf(A2.z, ex2f_(A2.w - tX), e);
            if (j - 1 < 255) e = fmaf(A1.z, ex2f_(A1.w - tX), e);
            if (i + 1 < 255 && j - 1 < 255)
                             e = fmaf(A2.x, ex2f_(A2.y - tX), e);
            X = e;
        }
        if (d == 510) X = (i + 1 == 255) ? 1.0f : 0.0f;

        // Z = E[d-1][i]
        float QY = (R0 - D0) * KE2;
        float QX = (Rx - Dx) * KE2;
        bool vZ = (i <= d - 1) && (d - 1 - i < 256);
        float Z = 0.0f;
        if (vZ) {
            float tZ = R1 * KE2;
            float e = 0.0f;
            if (i < 255)         e = fmaf(X, ex2f_(QX - tZ), e);
            if (d - 1 - i < 255) e = fmaf(Y, ex2f_(QY - tZ), e);
            if (i < 255 && d - 1 - i < 255)
                                 e = fmaf(A1.z, ex2f_(A1.w - tZ), e);
            Z = e;
        }

        if (vY) { accS += Y; float dw = (float)(i - j);       accW = fmaf(Y, dw * dw, accW); }
        if (vZ) { accS += Z; float dw = (float)(i - (j - 1)); accW = fmaf(Z, dw * dw, accW); }

        sP4[p & 1][i] = make_float4(Y, QY, Z, (R1 - D1) * KE2);
        __syncthreads();
    };

#pragma unroll 1
    for (int g = 0; g < 63; g++) {
#pragma unroll
        for (int k = 0; k < 4; k++) bstep(g * 4 + k, k);
    }
    bstep(252, 0); bstep(253, 1); bstep(254, 2);

    // Epilogue: diag 0, cell (0,0) (omega weight 0). Phase 254 buffer = sP4[0].
    if (i == 0) {
        float tY = rR0[3] * KE2;   // R[0][0]
        float4 B0 = sP4[0][0];     // (E2[0], Q2[0], E1[0], Q1[0])
        float4 B1 = sP4[0][1];     // (E2[1], Q2[1], E1[1], Q1[1])
        float e = 0.0f;
        e = fmaf(B1.z, ex2f_(B1.w - tY), e);   // (1,0) diag 1
        e = fmaf(B0.z, ex2f_(B0.w - tY), e);   // (0,1) diag 1
        e = fmaf(B1.x, ex2f_(B1.y - tY), e);   // (1,1) diag 2
        accS += e;
    }

    accW *= (1.0f / (255.0f * 255.0f));

#pragma unroll
    for (int off = 16; off; off >>= 1) {
        accS += __shfl_down_sync(0xFFFFFFFFu, accS, off);
        accW += __shfl_down_sync(0xFFFFFFFFu, accW, off);
    }
    const int w = i >> 5, l = i & 31;
    if (l == 0) { red[w] = accS; red[w + 8] = accW; }
    __syncthreads();
    if (i == 0) {
        float s = 0.0f, wv = 0.0f;
#pragma unroll
        for (int q = 0; q < 8; q++) { s += red[q]; wv += red[q + 8]; }
        g_den[b] = s;
        g_num[b] = wv;
    }
}

// ---------------------------------------------------------------------------
// Kernel 4: final scalar.
// ---------------------------------------------------------------------------
__global__ void final_kernel(float* __restrict__ out)
{
    __shared__ float red[4];
    const int t = threadIdx.x;   // 128 threads, one per batch

    float shape = g_shape[t] * (1.0f / 256.0f);
    float den   = g_den[t]   * (1.0f / 256.0f);
    float num   = g_num[t]   * (1.0f / 256.0f);
    float temporal = num / fmaxf(den, 1e-8f);
    float val = 0.5f * shape + 0.5f * temporal;

#pragma unroll
    for (int off = 16; off; off >>= 1)
        val += __shfl_down_sync(0xFFFFFFFFu, val, off);
    if ((t & 31) == 0) red[t >> 5] = val;
    __syncthreads();
    if (t == 0)
        out[0] = (red[0] + red[1] + red[2] + red[3]) * (1.0f / 128.0f);
}

// ---------------------------------------------------------------------------
extern "C" void kernel_launch(void* const* d_in, const int* in_sizes, int n_in,
                              void* d_out, int out_size)
{
    const float* preds   = (const float*)d_in[0];
    const float* targets = (const float*)d_in[1];

    dist_kernel<<<dim3(4, 4, BATCH), 256>>>(preds, targets);
    fwd_kernel<<<BATCH, 256>>>();
    bwd_kernel<<<BATCH, 256>>>();
    final_kernel<<<1, 128>>>((float*)d_out);
}

// round 12
// speedup vs baseline: 3.2696x; 1.0100x over previous
#include <cuda_runtime.h>

// ---------------------------------------------------------------------------
// DILATE loss. B=128, T=256, D=64, gamma=0.01, alpha=0.5, eps=1e-8, BIG=1e10.
//
// Key identity: the softmin weights of the FORWARD pass are exactly the
// backward gradient edge weights. fwd stores (w_dg, w_up) per cell (float2);
// bwd is then a pure linear recurrence on pre-multiplied products E*w —
// no exp, no R, no D needed in bwd.
// ---------------------------------------------------------------------------

#define BATCH 128
#define TLEN  256
#define NDIAG 511            // 2*TLEN - 1
#define PAD   16             // diag padding each side (ring overshoot)
#define NDIAGT (NDIAG + 2 * PAD)
#define BIGV  1e10f
// exp(x/gamma) = exp2(x * KE2);  KE2 = (1/gamma)*log2(e)
#define KE2   144.26950408889634f
// gamma * ln(2)
#define KL    0.006931471805599453f

__device__ float  g_D[(size_t)BATCH * NDIAGT * TLEN];
__device__ float2 g_W[(size_t)BATCH * NDIAGT * TLEN];   // (w_diag, w_up) per cell
__device__ float  g_shape[BATCH];
__device__ float  g_num[BATCH];
__device__ float  g_den[BATCH];

__device__ __forceinline__ size_t DI(int b, int d, int i) {
    return ((size_t)b * NDIAGT + (d + PAD)) * TLEN + i;
}

__device__ __forceinline__ float ex2f_(float x) {
    float y; asm("ex2.approx.ftz.f32 %0, %1;" : "=f"(y) : "f"(x)); return y;
}
__device__ __forceinline__ float lg2f_(float x) {
    float y; asm("lg2.approx.ftz.f32 %0, %1;" : "=f"(y) : "f"(x)); return y;
}
__device__ __forceinline__ float rcpf_(float x) {
    float y; asm("rcp.approx.ftz.f32 %0, %1;" : "=f"(y) : "f"(x)); return y;
}

// ---------------------------------------------------------------------------
// Kernel 1: pairwise squared distances in diagonal layout (float4 smem).
// ---------------------------------------------------------------------------
__global__ __launch_bounds__(256) void dist_kernel(
    const float* __restrict__ preds, const float* __restrict__ targets)
{
    __shared__ float pool[2 * 64 * 68 + 128];
    float*  ps  = pool;                   // [64][68]
    float*  ts  = pool + 64 * 68;
    float*  pn  = pool + 2 * 64 * 68;     // [64]
    float*  tn  = pn + 64;
    float4* ps4 = (float4*)ps;            // pitch 17
    float4* ts4 = (float4*)ts;

    const int b  = blockIdx.z;
    const int i0 = blockIdx.y * 64;
    const int j0 = blockIdx.x * 64;
    const int tid = threadIdx.x;

    const float4* pb4 = (const float4*)(preds   + (size_t)b * TLEN * 64 + (size_t)i0 * 64);
    const float4* tb4 = (const float4*)(targets + (size_t)b * TLEN * 64 + (size_t)j0 * 64);

#pragma unroll
    for (int q = 0; q < 4; q++) {
        int idx = q * 256 + tid;          // 0..1023 float4s
        int r = idx >> 4, c4 = idx & 15;
        ps4[r * 17 + c4] = pb4[idx];
        ts4[r * 17 + c4] = tb4[idx];
    }
    __syncthreads();

    if (tid < 128) {
        const float* src = (tid < 64) ? ps : ts;
        float* dst = (tid < 64) ? pn : tn;
        int r = tid & 63;
        float s = 0.0f;
#pragma unroll
        for (int k = 0; k < 64; k++) { float v = src[r * 68 + k]; s = fmaf(v, v, s); }
        dst[r] = s;
    }
    __syncthreads();

    const int tx = tid & 15, ty = tid >> 4;
    const int ib = ty * 4, jb = tx * 4;

    float acc[4][4];
#pragma unroll
    for (int r = 0; r < 4; r++)
#pragma unroll
        for (int c = 0; c < 4; c++) acc[r][c] = 0.0f;

#pragma unroll 4
    for (int kq = 0; kq < 16; kq++) {
        float4 pv[4], tv[4];
#pragma unroll
        for (int r = 0; r < 4; r++) pv[r] = ps4[(ib + r) * 17 + kq];
#pragma unroll
        for (int c = 0; c < 4; c++) tv[c] = ts4[(jb + c) * 17 + kq];
#pragma unroll
        for (int r = 0; r < 4; r++)
#pragma unroll
            for (int c = 0; c < 4; c++) {
                acc[r][c] = fmaf(pv[r].x, tv[c].x, acc[r][c]);
                acc[r][c] = fmaf(pv[r].y, tv[c].y, acc[r][c]);
                acc[r][c] = fmaf(pv[r].z, tv[c].z, acc[r][c]);
                acc[r][c] = fmaf(pv[r].w, tv[c].w, acc[r][c]);
            }
    }

    float pnr[4], tnr[4];
#pragma unroll
    for (int r = 0; r < 4; r++) pnr[r] = pn[ib + r];
#pragma unroll
    for (int c = 0; c < 4; c++) tnr[c] = tn[jb + c];

    __syncthreads();

    // Stage tile diagonally: buf[tdd][ii], tdd = local i+j (0..126), pitch 65.
    float* buf = pool;
#pragma unroll
    for (int r = 0; r < 4; r++)
#pragma unroll
        for (int c = 0; c < 4; c++) {
            int ii = ib + r, jj = jb + c;
            float dv = pnr[r] + tnr[c] - 2.0f * acc[r][c];
            buf[(ii + jj) * 65 + ii] = fmaxf(dv, 0.0f);
        }
    __syncthreads();

    for (int base = 0; base < 128; base += 4) {
        int tdd = base + (tid >> 6);
        int ii  = tid & 63;
        if (tdd < 127) {
            int jj = tdd - ii;
            if (jj >= 0 && jj < 64)
                g_D[DI(b, i0 + j0 + tdd, i0 + ii)] = buf[tdd * 65 + ii];
        }
    }
}

// ---------------------------------------------------------------------------
// Kernel 2: soft-DTW forward. Phase p computes diags d=2p (Y), d+1 (Z) with
// halo X = R[d][i-1]. Ping-pong float2 smem sP[p&1][i+2] = (R_d[i], R_{d+1}[i]).
// Emits per-cell weights W=(w_dg,w_up) to g_W (deferred 1 phase). No g_R.
// ---------------------------------------------------------------------------
__global__ __launch_bounds__(256) void fwd_kernel()
{
    __shared__ float2 sP[2][260];   // [0..1] = BIG pad (never overwritten)
    const int b = blockIdx.x;
    const int i = threadIdx.x;

    for (int q = i; q < 2 * 260 * 2; q += 256) ((float*)sP)[q] = BIGV;
    __syncthreads();

    const float* Dbase  = g_D + ((size_t)b * NDIAGT + PAD) * TLEN;
    const float* Dp     = Dbase + i;
    const float* DpH    = Dbase + i - 1;   // halo column (pad rows keep i=0 safe)
    float2*      Wp     = g_W + ((size_t)b * NDIAGT + PAD) * TLEN + i;

    float rA[4], rB[4], rH[4];
#pragma unroll
    for (int k = 0; k < 4; k++) {
        rA[k] = Dp[(2 * k) * TLEN];
        rB[k] = Dp[(2 * k + 1) * TLEN];
        rH[k] = DpH[(2 * k) * TLEN];
    }

    float2 qY = make_float2(0.f, 0.f), qZ = make_float2(0.f, 0.f);

    auto fstep = [&](int p, int k) {
        const int d = 2 * p;
        // Deferred weight stores of previous phase (post-barrier).
        if (p >= 1) {
            Wp[(size_t)(d - 2) * TLEN] = qY;
            Wp[(size_t)(d - 1) * TLEN] = qZ;
        }

        float DY = rA[k], DZ = rB[k], DXv = rH[k];
        rA[k] = Dp[(d + 8) * TLEN];
        rB[k] = Dp[(d + 9) * TLEN];
        rH[k] = DpH[(d + 8) * TLEN];

        const float2* sPp = sP[(p + 1) & 1];
        float2 P0 = sPp[i];       // (R[d-2][i-2], R[d-1][i-2])
        float2 P1 = sPp[i + 1];   // (R[d-2][i-1], R[d-1][i-1])
        float2 P2 = sPp[i + 2];   // (R[d-2][i],   R[d-1][i])

        // X = R[d][i-1] (halo; no weights needed)
        bool vX = (i >= 1) && (i <= d + 1) && (d - i < 255);
        float mx = fminf(P0.x, fminf(P0.y, P1.y));
        float sx = ex2f_((mx - P0.x) * KE2) + ex2f_((mx - P0.y) * KE2)
                 + ex2f_((mx - P1.y) * KE2);
        float x = mx - KL * lg2f_(sx) + DXv;
        if (d == 0) x = DXv;
        if (!vX) x = BIGV;

        // Y = R[d][i]  (preds: diag=P1.x, up=P1.y, left=P2.y)
        bool vY = (i <= d) && (d - i < 256);
        float my = fminf(P1.x, fminf(P1.y, P2.y));
        float e0 = ex2f_((my - P1.x) * KE2);
        float e1 = ex2f_((my - P1.y) * KE2);
        float e2 = ex2f_((my - P2.y) * KE2);
        float sy = e0 + e1 + e2;
        float y  = my - KL * lg2f_(sy) + DY;
        float ry = rcpf_(sy);
        float2 wY = make_float2(e0 * ry, e1 * ry);
        if (d == 0 && i == 0) y = DY;
        if (!vY) y = BIGV;

        // Z = R[d+1][i]  (preds: diag=P1.y, up=x, left=y)
        bool vZ = (i <= d + 1) && (d - i < 255);
        float mz = fminf(P1.y, fminf(x, y));
        float f0 = ex2f_((mz - P1.y) * KE2);
        float f1 = ex2f_((mz - x) * KE2);
        float f2 = ex2f_((mz - y) * KE2);
        float sz = f0 + f1 + f2;
        float z  = mz - KL * lg2f_(sz) + DZ;
        float rz = rcpf_(sz);
        float2 wZ = make_float2(f0 * rz, f1 * rz);
        if (!vZ) z = BIGV;

        sP[p & 1][i + 2] = make_float2(y, z);
        qY = wY; qZ = wZ;
        __syncthreads();
    };

#pragma unroll 1
    for (int g = 0; g < 63; g++) {
#pragma unroll
        for (int k = 0; k < 4; k++) fstep(g * 4 + k, k);
    }
    fstep(252, 0); fstep(253, 1); fstep(254, 2);

    // Flush phase 254's deferred weight stores.
    Wp[(size_t)508 * TLEN] = qY;
    Wp[(size_t)509 * TLEN] = qZ;

    // Epilogue: diag 510 (reads phase 254's buffer = sP[0]).
    {
        const float2* sPp = sP[0];
        float m = fminf(sPp[i + 1].x, fminf(sPp[i + 1].y, sPp[i + 2].y));
        float e0 = ex2f_((m - sPp[i + 1].x) * KE2);
        float e1 = ex2f_((m - sPp[i + 1].y) * KE2);
        float e2 = ex2f_((m - sPp[i + 2].y) * KE2);
        float s = e0 + e1 + e2;
        float y = m - KL * lg2f_(s) + rA[3];
        float rs = rcpf_(s);
        Wp[(size_t)510 * TLEN] = make_float2(e0 * rs, e1 * rs);
        if (i == 255) g_shape[b] = y;   // R[255,255]
    }
}

// ---------------------------------------------------------------------------
// Kernel 3: gradient, reverse. LINEAR recurrence on products:
// cell c stores (E_c*w_dg, E_c*w_up, E_c*w_lf); then
// E[d][i] = lf(d+1,i) + up(d+1,i+1) + dg(d+2,i+1).  No exp, no MUFU.
// Phase p: Y = E[d][i] (d=510-2p), Z = E[d-1][i], halo X = E[d][i+1].
// 8-phase register rings on the three g_W streams.
// ---------------------------------------------------------------------------
__global__ __launch_bounds__(256) void bwd_kernel()
{
    __shared__ float4 sY4[2][258];   // products of diag d   (slots 256,257 = 0)
    __shared__ float4 sZ4[2][258];   // products of diag d-1
    __shared__ float red[16];

    const int b = blockIdx.x;
    const int i = threadIdx.x;

    for (int q = i; q < 2 * 258 * 4 * 2; q += 256) ((float*)sY4)[q] = 0.0f;
    __syncthreads();

    const float2* Wb  = g_W + ((size_t)b * NDIAGT + PAD) * TLEN;
    const float2* W0p = Wb + i;        // stream at col i
    const float2* WXp = Wb + i + 1;    // halo col i+1 (overflow lands in-array, finite)

    float2 rW0[8], rW1[8], rWX[8];
#pragma unroll
    for (int k = 0; k < 8; k++) {
        rW0[k] = W0p[(size_t)(510 - 2 * k) * TLEN];
        rW1[k] = W0p[(size_t)(509 - 2 * k) * TLEN];
        rWX[k] = WXp[(size_t)(510 - 2 * k) * TLEN];
    }

    float accS = 0.0f, accW = 0.0f;

    auto bstep = [&](int p, int k) {
        const int d = 510 - 2 * p;
        float2 wYv = rW0[k], wZv = rW1[k], wXv = rWX[k];
        rW0[k] = W0p[(size_t)(d - 16) * TLEN];
        rW1[k] = W0p[(size_t)(d - 17) * TLEN];
        rWX[k] = WXp[(size_t)(d - 16) * TLEN];

        const float4* pY = sY4[(p + 1) & 1];   // diag d+2 products
        const float4* pZ = sZ4[(p + 1) & 1];   // diag d+1 products

        float4 Z1 = pZ[i + 1];
        // Y = E[d][i]
        float Y = pZ[i].z + Z1.y + pY[i + 1].x;
        if (d == 510) Y = (i == 255) ? 1.0f : 0.0f;
        // X = E[d][i+1] (halo)
        float X = Z1.z + pZ[i + 2].y + pY[i + 2].x;
        if (d == 510) X = (i + 1 == 255) ? 1.0f : 0.0f;

        float wlfY = 1.0f - wYv.x - wYv.y;
        // Z = E[d-1][i] = dg(d+1,i+1) + X*w_up(d,i+1) + Y*w_lf(d,i)
        float Z = Z1.x + X * wXv.y + Y * wlfY;

        bool vY = (i <= d) && (d - i < 256);
        bool vZ = (i <= d - 1) && (d - 1 - i < 256);
        Y = vY ? Y : 0.0f;
        Z = vZ ? Z : 0.0f;

        accS += Y + Z;
        float dwy = (float)(2 * i - d);
        float dwz = (float)(2 * i - d + 1);
        accW = fmaf(Y, dwy * dwy, accW);
        accW = fmaf(Z, dwz * dwz, accW);

        float wlfZ = 1.0f - wZv.x - wZv.y;
        sY4[p & 1][i] = make_float4(Y * wYv.x, Y * wYv.y, Y * wlfY, 0.0f);
        sZ4[p & 1][i] = make_float4(Z * wZv.x, Z * wZv.y, Z * wlfZ, 0.0f);
        __syncthreads();
    };

#pragma unroll 1
    for (int g = 0; g < 31; g++) {
#pragma unroll
        for (int k = 0; k < 8; k++) bstep(g * 8 + k, k);
    }
#pragma unroll
    for (int k = 0; k < 7; k++) bstep(248 + k, k);   // p = 248..254 (d = 14..2)

    // Epilogue: E[0,0] (omega weight 0). Phase 254 buffers = index 0.
    if (i == 0) {
        float E00 = sZ4[0][0].z + sZ4[0][1].y + sY4[0][1].x;
        accS += E00;
    }

    accW *= (1.0f / (255.0f * 255.0f));

#pragma unroll
    for (int off = 16; off; off >>= 1) {
        accS += __shfl_down_sync(0xFFFFFFFFu, accS, off);
        accW += __shfl_down_sync(0xFFFFFFFFu, accW, off);
    }
    const int w = i >> 5, l = i & 31;
    if (l == 0) { red[w] = accS; red[w + 8] = accW; }
    __syncthreads();
    if (i == 0) {
        float s = 0.0f, wv = 0.0f;
#pragma unroll
        for (int q = 0; q < 8; q++) { s += red[q]; wv += red[q + 8]; }
        g_den[b] = s;
        g_num[b] = wv;
    }
}

// ---------------------------------------------------------------------------
// Kernel 4: final scalar.
// ---------------------------------------------------------------------------
__global__ void final_kernel(float* __restrict__ out)
{
    __shared__ float red[4];
    const int t = threadIdx.x;   // 128 threads, one per batch

    float shape = g_shape[t] * (1.0f / 256.0f);
    float den   = g_den[t]   * (1.0f / 256.0f);
    float num   = g_num[t]   * (1.0f / 256.0f);
    float temporal = num / fmaxf(den, 1e-8f);
    float val = 0.5f * shape + 0.5f * temporal;

#pragma unroll
    for (int off = 16; off; off >>= 1)
        val += __shfl_down_sync(0xFFFFFFFFu, val, off);
    if ((t & 31) == 0) red[t >> 5] = val;
    __syncthreads();
    if (t == 0)
        out[0] = (red[0] + red[1] + red[2] + red[3]) * (1.0f / 128.0f);
}

// ---------------------------------------------------------------------------
extern "C" void kernel_launch(void* const* d_in, const int* in_sizes, int n_in,
                              void* d_out, int out_size)
{
    const float* preds   = (const float*)d_in[0];
    const float* targets = (const float*)d_in[1];

    dist_kernel<<<dim3(4, 4, BATCH), 256>>>(preds, targets);
    fwd_kernel<<<BATCH, 256>>>();
    bwd_kernel<<<BATCH, 256>>>();
    final_kernel<<<1, 128>>>((float*)d_out);
}